// round 7
// baseline (speedup 1.0000x reference)
#include <cuda_runtime.h>
#include <cstdint>

#define BN 1024
#define DN 256
#define LN 32

// Scratch (no allocations allowed)
__device__ int g_negcnt[LN];            // #rows with label != l
__device__ int g_neglist[LN * BN];      // stable-ordered negative row indices
__device__ int g_poscnt[LN];            // #anchors with label == l
__device__ int g_poslist[LN * BN];      // anchor row indices
__device__ int g_ready = 0;             // producer flag (monotone across replays)

// ---------------------------------------------------------------------------
// Threefry-2x32 (JAX partitionable scheme), key = (0, 42).
// bits(t) = out0 ^ out1 of threefry2x32(key, (hi=0, lo=t)).
// ---------------------------------------------------------------------------
__device__ __forceinline__ uint32_t rotl32(uint32_t x, int r) {
    return (x << r) | (x >> (32 - r));
}

__device__ __forceinline__ uint32_t threefry_bits32(uint32_t x0, uint32_t x1) {
    const uint32_t k0 = 0u, k1 = 42u;
    const uint32_t k2 = k0 ^ k1 ^ 0x1BD11BDAu;
    x0 += k0; x1 += k1;
#define TF_ROUND(r) { x0 += x1; x1 = rotl32(x1, (r)); x1 ^= x0; }
    TF_ROUND(13) TF_ROUND(15) TF_ROUND(26) TF_ROUND(6)
    x0 += k1; x1 += k2 + 1u;
    TF_ROUND(17) TF_ROUND(29) TF_ROUND(16) TF_ROUND(24)
    x0 += k2; x1 += k0 + 2u;
    TF_ROUND(13) TF_ROUND(15) TF_ROUND(26) TF_ROUND(6)
    x0 += k0; x1 += k1 + 3u;
    TF_ROUND(17) TF_ROUND(29) TF_ROUND(16) TF_ROUND(24)
    x0 += k1; x1 += k2 + 4u;
    TF_ROUND(13) TF_ROUND(15) TF_ROUND(26) TF_ROUND(6)
    x0 += k2; x1 += k0 + 5u;
#undef TF_ROUND
    return x0 ^ x1;
}

// ---------------------------------------------------------------------------
// In-kernel list producer: 256 threads build the stable negative/anchor lists
// for one label. Thread t owns rows 4t..4t+3 (contiguous -> lane order == row
// order, so warp scans of per-thread counts give stable ranks).
// ---------------------------------------------------------------------------
__device__ void produce_lists(const int* __restrict__ label, int l) {
    int t = threadIdx.x;          // 0..255
    int lane = t & 31;
    int w    = t >> 5;            // 0..7
    __shared__ int wtot[8];
    __shared__ int wpre[8];

    int4 lb = ((const int4*)label)[t];
    int m0 = (lb.x != l), m1 = (lb.y != l), m2 = (lb.z != l), m3 = (lb.w != l);
    int cnt = m0 + m1 + m2 + m3;

    // warp inclusive scan of per-thread neg counts
    int s = cnt;
    #pragma unroll
    for (int o = 1; o < 32; o <<= 1) {
        int n = __shfl_up_sync(0xffffffffu, s, o);
        if (lane >= o) s += n;
    }
    if (lane == 31) wtot[w] = s;
    __syncthreads();
    if (t < 8) {
        int e = 0;
        #pragma unroll
        for (int k = 0; k < 8; k++) if (k < t) e += wtot[k];
        wpre[t] = e;
        if (t == 7) {
            int total = e + wtot[7];
            g_negcnt[l] = total;
            g_poscnt[l] = BN - total;
        }
    }
    __syncthreads();

    int negbase = wpre[w] + (s - cnt);   // exclusive neg rank of row 4t
    int rowbase = 4 * t;
    int posbase = rowbase - negbase;     // exclusive pos rank
    int* __restrict__ ng = g_neglist + l * BN;
    int* __restrict__ pg = g_poslist + l * BN;
    int nb = negbase, pb = posbase;
    if (m0) ng[nb++] = rowbase + 0; else pg[pb++] = rowbase + 0;
    if (m1) ng[nb++] = rowbase + 1; else pg[pb++] = rowbase + 1;
    if (m2) ng[nb++] = rowbase + 2; else pg[pb++] = rowbase + 2;
    if (m3) ng[nb++] = rowbase + 3; else pg[pb++] = rowbase + 3;

    __syncthreads();
    if (t == 0) {
        __threadfence();                       // publish list writes
        atomicAdd(&g_ready, 1);
    }
}

// ---------------------------------------------------------------------------
// Fused kernel. Blocks (x<32, y==0) first produce the lists for label x, then
// every block waits for g_ready (pass-through on graph replays: lists are
// rewritten with identical values, 4B-aligned stores are atomic) and runs the
// R5 gather body: block = (j, l), 8 warps stride the anchor loop, streaming
// stores, smem-cached source row + anchor list.
// ---------------------------------------------------------------------------
__global__ void fused_kernel(const float* __restrict__ embs,
                             const int* __restrict__ label,
                             float* __restrict__ out,
                             int max_count) {
    int j = blockIdx.x;
    int l = blockIdx.y;

    if (l == 0 && j < LN)
        produce_lists(label, j);

    // Wait for all 32 producers (first launch only; replays pass through).
    if (threadIdx.x == 0) {
        while (*(volatile int*)&g_ready < LN) { }
        __threadfence();                       // acquire
    }
    __syncthreads();

    int nc = g_negcnt[l];
    int pc = g_poscnt[l];
    if (pc == 0) return;

    int lane = threadIdx.x & 31;
    int w    = threadIdx.x >> 5;

    __shared__ float4 srow[DN / 4];   // 1 KB
    __shared__ int    spos[BN];       // anchor list (pc entries used)

    for (int t = threadIdx.x; t < pc; t += 256)
        spos[t] = g_poslist[l * BN + t];
    if (j < nc && threadIdx.x < DN / 4) {
        int src = g_neglist[l * BN + j];
        srow[threadIdx.x] = ((const float4*)embs)[(size_t)src * (DN / 4) + threadIdx.x];
    }
    __syncthreads();

    if (j < nc) {
        float4 v0 = srow[lane];
        float4 v1 = srow[lane + 32];
        for (int a = w; a < pc; a += 8) {
            int i = spos[a];
            float4* dst = (float4*)out + ((size_t)i * max_count + j) * (DN / 4);
            __stcs(dst + lane,      v0);
            __stcs(dst + lane + 32, v1);
        }
    } else {
        // padded tail: per-anchor uniform resample among the nc negatives
        for (int a = w; a < pc; a += 8) {
            int i = spos[a];
            int p = 0;
            if (lane == 0) {
                uint32_t t = (uint32_t)(i * max_count + j);   // row-major flat idx
                uint32_t bits = threefry_bits32(0u, t);
                float u = __uint_as_float((bits >> 9) | 0x3F800000u) - 1.0f;
                p = (int)__fmul_rn(u, (float)nc);             // trunc, matches XLA
                int cap = nc - 1;
                if (p > cap) p = cap;
            }
            p = __shfl_sync(0xffffffffu, p, 0);
            int src = g_neglist[l * BN + p];
            const float4* s = (const float4*)embs + (size_t)src * (DN / 4);
            float4*     dst = (float4*)out + ((size_t)i * max_count + j) * (DN / 4);
            __stcs(dst + lane,      s[lane]);
            __stcs(dst + lane + 32, s[lane + 32]);
        }
    }
}

// ---------------------------------------------------------------------------
extern "C" void kernel_launch(void* const* d_in, const int* in_sizes, int n_in,
                              void* d_out, int out_size) {
    const float* embs  = (const float*)d_in[0];
    const int*   label = (const int*)d_in[1];
    if (n_in >= 2 && in_sizes[0] == BN && in_sizes[1] == BN * DN) {
        embs  = (const float*)d_in[1];
        label = (const int*)d_in[0];
    }

    int max_count = out_size / (BN * DN);

    dim3 grid(max_count, LN);
    fused_kernel<<<grid, 256>>>(embs, label, (float*)d_out, max_count);
}

// round 8
// speedup vs baseline: 1.0845x; 1.0845x over previous
#include <cuda_runtime.h>
#include <cstdint>

#define BN 1024
#define DN 256
#define LN 32

// Scratch (no allocations allowed)
__device__ int g_negcnt[LN];            // #rows with label != l
__device__ int g_neglist[LN * BN];      // stable-ordered negative row indices
__device__ int g_poscnt[LN];            // #anchors with label == l
__device__ int g_poslist[LN * BN];      // anchor row indices

// ---------------------------------------------------------------------------
// Kernel 1: per-label lists + counts. One block per label, 1024 threads.
// Stable block-wide compaction via ballot/popc + warp-sum scan.
// Fires the PDL completion trigger so the gather grid launches ASAP.
// ---------------------------------------------------------------------------
__global__ void lists_kernel(const int* __restrict__ label) {
    int l = blockIdx.x;
    int t = threadIdx.x;
    int lane = t & 31;
    int wid  = t >> 5;
    __shared__ int wpre[32];
    __shared__ int s_total;

    bool neg = (label[t] != l);
    unsigned m = __ballot_sync(0xffffffffu, neg);
    int nrank = __popc(m & ((1u << lane) - 1u));
    if (lane == 0) wpre[wid] = __popc(m);
    __syncthreads();
    if (wid == 0) {
        int v = wpre[lane];
        int s = v;
        #pragma unroll
        for (int o = 1; o < 32; o <<= 1) {
            int n = __shfl_up_sync(0xffffffffu, s, o);
            if (lane >= o) s += n;
        }
        if (lane == 31) s_total = s;
        wpre[lane] = s - v;
    }
    __syncthreads();

    if (neg) {
        g_neglist[l * BN + wpre[wid] + nrank] = t;
    } else {
        int ppre  = (wid << 5) - wpre[wid];
        int prank = lane - nrank;
        g_poslist[l * BN + ppre + prank] = t;
    }
    if (t == 0) {
        g_negcnt[l] = s_total;
        g_poscnt[l] = BN - s_total;
    }
#if __CUDA_ARCH__ >= 900
    __syncthreads();
    cudaTriggerProgrammaticLaunchCompletion();   // release dependent grid early
#endif
}

// ---------------------------------------------------------------------------
// Threefry-2x32 (JAX partitionable scheme), key = (0, 42).
// bits(t) = out0 ^ out1 of threefry2x32(key, (hi=0, lo=t)).
// ---------------------------------------------------------------------------
__device__ __forceinline__ uint32_t rotl32(uint32_t x, int r) {
    return (x << r) | (x >> (32 - r));
}

__device__ __forceinline__ uint32_t threefry_bits32(uint32_t x0, uint32_t x1) {
    const uint32_t k0 = 0u, k1 = 42u;
    const uint32_t k2 = k0 ^ k1 ^ 0x1BD11BDAu;
    x0 += k0; x1 += k1;
#define TF_ROUND(r) { x0 += x1; x1 = rotl32(x1, (r)); x1 ^= x0; }
    TF_ROUND(13) TF_ROUND(15) TF_ROUND(26) TF_ROUND(6)
    x0 += k1; x1 += k2 + 1u;
    TF_ROUND(17) TF_ROUND(29) TF_ROUND(16) TF_ROUND(24)
    x0 += k2; x1 += k0 + 2u;
    TF_ROUND(13) TF_ROUND(15) TF_ROUND(26) TF_ROUND(6)
    x0 += k0; x1 += k1 + 3u;
    TF_ROUND(17) TF_ROUND(29) TF_ROUND(16) TF_ROUND(24)
    x0 += k1; x1 += k2 + 4u;
    TF_ROUND(13) TF_ROUND(15) TF_ROUND(26) TF_ROUND(6)
    x0 += k2; x1 += k0 + 5u;
#undef TF_ROUND
    return x0 ^ x1;
}

// ---------------------------------------------------------------------------
// Kernel 2: gather with source-row reuse (R6 body) + warp-parallel tail RNG.
// Block = (j = blockIdx.x, label l = blockIdx.y), 256 threads = 8 warps.
// PDL-gated on lists_kernel via cudaGridDependencySynchronize().
// ---------------------------------------------------------------------------
__global__ void gather_kernel(const float* __restrict__ embs,
                              float* __restrict__ out,
                              int max_count) {
#if __CUDA_ARCH__ >= 900
    cudaGridDependencySynchronize();
#endif
    int j = blockIdx.x;
    int l = blockIdx.y;
    int nc = g_negcnt[l];
    int pc = g_poscnt[l];
    if (pc == 0) return;

    int lane = threadIdx.x & 31;
    int w    = threadIdx.x >> 5;

    __shared__ float4 srow[DN / 4];   // 1 KB
    __shared__ int    spos[BN];       // anchor list (pc entries used)

    for (int t = threadIdx.x; t < pc; t += 256)
        spos[t] = g_poslist[l * BN + t];
    if (j < nc && threadIdx.x < DN / 4) {
        int src = g_neglist[l * BN + j];
        srow[threadIdx.x] = ((const float4*)embs)[(size_t)src * (DN / 4) + threadIdx.x];
    }
    __syncthreads();

    if (j < nc) {
        float4 v0 = srow[lane];
        float4 v1 = srow[lane + 32];
        for (int a = w; a < pc; a += 8) {
            int i = spos[a];
            float4* dst = (float4*)out + ((size_t)i * max_count + j) * (DN / 4);
            __stcs(dst + lane,      v0);
            __stcs(dst + lane + 32, v1);
        }
    } else {
        // padded tail: per-anchor uniform resample among the nc negatives.
        // Compute all of this warp's anchor resample indices warp-parallel
        // (lane k handles anchor a = w + 8k), then loop the row copies.
        int a_lane = w + 8 * lane;                 // anchor index for this lane
        int src_lane = 0;
        if (a_lane < pc) {
            int i = spos[a_lane];
            uint32_t t = (uint32_t)(i * max_count + j);   // row-major flat idx
            uint32_t bits = threefry_bits32(0u, t);
            float u = __uint_as_float((bits >> 9) | 0x3F800000u) - 1.0f;
            int p = (int)__fmul_rn(u, (float)nc);         // trunc, matches XLA
            int cap = nc - 1;
            if (p > cap) p = cap;
            src_lane = g_neglist[l * BN + p];
        }
        int k = 0;
        for (int a = w; a < pc; a += 8, k++) {
            int i   = spos[a];
            int src = __shfl_sync(0xffffffffu, src_lane, k);
            const float4* s = (const float4*)embs + (size_t)src * (DN / 4);
            float4*     dst = (float4*)out + ((size_t)i * max_count + j) * (DN / 4);
            __stcs(dst + lane,      s[lane]);
            __stcs(dst + lane + 32, s[lane + 32]);
        }
    }
}

// ---------------------------------------------------------------------------
extern "C" void kernel_launch(void* const* d_in, const int* in_sizes, int n_in,
                              void* d_out, int out_size) {
    const float* embs  = (const float*)d_in[0];
    const int*   label = (const int*)d_in[1];
    if (n_in >= 2 && in_sizes[0] == BN && in_sizes[1] == BN * DN) {
        embs  = (const float*)d_in[1];
        label = (const int*)d_in[0];
    }

    int max_count = out_size / (BN * DN);

    lists_kernel<<<LN, BN>>>(label);

    dim3 grid(max_count, LN);

    // PDL launch: gather blocks spin up while lists_kernel drains; ordering
    // comes from the in-kernel cudaGridDependencySynchronize().
    cudaLaunchConfig_t cfg = {};
    cfg.gridDim  = grid;
    cfg.blockDim = dim3(256, 1, 1);
    cfg.dynamicSmemBytes = 0;
    cfg.stream = 0;
    cudaLaunchAttribute attr[1];
    attr[0].id = cudaLaunchAttributeProgrammaticStreamSerialization;
    attr[0].val.programmaticStreamSerializationAllowed = 1;
    cfg.attrs = attr;
    cfg.numAttrs = 1;

    cudaError_t err = cudaLaunchKernelEx(&cfg, gather_kernel,
                                         embs, (float*)d_out, max_count);
    if (err != cudaSuccess) {
        gather_kernel<<<grid, 256>>>(embs, (float*)d_out, max_count);
    }
}